// round 6
// baseline (speedup 1.0000x reference)
#include <cuda_runtime.h>
#include <cuda_bf16.h>
#include <math.h>
#include <cstdint>

// ---------------- dimensions ----------------
#define DB 8
#define DM 1024
#define DD 768
#define DN 64
#define DP 16
#define DH 1536
#define DS 1024   // n*p

// ---------------- scratch ----------------
__device__ float g_logits[DB * DM * DS];
__device__ float g_Xs[DB * DS * DD];
// bf16 hi/lo planes (raw u16)
__device__ unsigned short g_xh[DB * DM * DD],  g_xl[DB * DM * DD];
__device__ unsigned short g_ph[DN * DP * DD],  g_pl[DN * DP * DD];
__device__ unsigned short g_Ch[DB * DM * DS],  g_Cl[DB * DM * DS];
__device__ unsigned short g_Dh[DB * DM * DS],  g_Dl[DB * DM * DS];
__device__ unsigned short g_LNh[DN * DB * DP * DD], g_LNl[DN * DB * DP * DD];
__device__ unsigned short g_hh[DN * 128 * DH], g_hl[DN * 128 * DH];
__device__ unsigned short g_Yh[DB * DS * DD],  g_Yl[DB * DS * DD];

// ================= helpers =================
__device__ __forceinline__ uint32_t smem_to_u32(const void* p) {
    uint32_t a;
    asm("{ .reg .u64 t; cvta.to.shared.u64 t, %1; cvt.u32.u64 %0, t; }" : "=r"(a) : "l"(p));
    return a;
}

// fast split: hi = truncate-to-bf16 (bit mask), lo = rn(x - hi)
__device__ __forceinline__ void split4(float4 v, uint32_t& h01, uint32_t& h23,
                                       uint32_t& l01, uint32_t& l23) {
    uint32_t ux = __float_as_uint(v.x), uy = __float_as_uint(v.y);
    uint32_t uz = __float_as_uint(v.z), uw = __float_as_uint(v.w);
    h01 = __byte_perm(ux, uy, 0x7632);
    h23 = __byte_perm(uz, uw, 0x7632);
    float hx = __uint_as_float(ux & 0xFFFF0000u);
    float hy = __uint_as_float(uy & 0xFFFF0000u);
    float hz = __uint_as_float(uz & 0xFFFF0000u);
    float hw = __uint_as_float(uw & 0xFFFF0000u);
    asm("cvt.rn.bf16x2.f32 %0, %1, %2;" : "=r"(l01) : "f"(v.y - hy), "f"(v.x - hx));
    asm("cvt.rn.bf16x2.f32 %0, %1, %2;" : "=r"(l23) : "f"(v.w - hw), "f"(v.z - hz));
}

// scalar split to raw u16
__device__ __forceinline__ void split1(float v, unsigned short& h, unsigned short& lo) {
    uint32_t uv = __float_as_uint(v);
    h = (unsigned short)(uv >> 16);
    float hf = __uint_as_float(uv & 0xFFFF0000u);
    asm("cvt.rn.bf16.f32 %0, %1;" : "=h"(lo) : "f"(v - hf));
}

__device__ __forceinline__ void ldsm_x4(uint32_t* r, uint32_t addr) {
    asm volatile("ldmatrix.sync.aligned.m8n8.x4.shared.b16 {%0,%1,%2,%3}, [%4];"
                 : "=r"(r[0]), "=r"(r[1]), "=r"(r[2]), "=r"(r[3]) : "r"(addr));
}
__device__ __forceinline__ void ldsm_x4_t(uint32_t* r, uint32_t addr) {
    asm volatile("ldmatrix.sync.aligned.m8n8.x4.trans.shared.b16 {%0,%1,%2,%3}, [%4];"
                 : "=r"(r[0]), "=r"(r[1]), "=r"(r[2]), "=r"(r[3]) : "r"(addr));
}
__device__ __forceinline__ void mma_bf16(float* d, const uint32_t* a, const uint32_t* b) {
    asm volatile(
        "mma.sync.aligned.m16n8k16.row.col.f32.bf16.bf16.f32 "
        "{%0,%1,%2,%3}, {%4,%5,%6,%7}, {%8,%9}, {%0,%1,%2,%3};"
        : "+f"(d[0]), "+f"(d[1]), "+f"(d[2]), "+f"(d[3])
        : "r"(a[0]), "r"(a[1]), "r"(a[2]), "r"(a[3]), "r"(b[0]), "r"(b[1]));
}

// ================= elementwise kernels =================
__global__ void convert_split_kernel(const float* __restrict__ X, unsigned short* __restrict__ H,
                                     unsigned short* __restrict__ L, int n4) {
    int i = blockIdx.x * blockDim.x + threadIdx.x;
    if (i >= n4) return;
    float4 v = ((const float4*)X)[i];
    uint32_t h01, h23, l01, l23;
    split4(v, h01, h23, l01, l23);
    ((uint2*)H)[i] = make_uint2(h01, h23);
    ((uint2*)L)[i] = make_uint2(l01, l23);
}

__global__ void phi_norm_kernel(const float* __restrict__ phi,
                                unsigned short* __restrict__ H, unsigned short* __restrict__ L) {
    int i = blockIdx.x * blockDim.x + threadIdx.x;
    if (i >= DP * DD) return;
    float s = 0.f;
#pragma unroll 4
    for (int n = 0; n < DN; n++) { float v = phi[n * (DP * DD) + i]; s += v * v; }
    float r = rsqrtf(s + 1e-6f);
#pragma unroll 4
    for (int n = 0; n < DN; n++) {
        float v = phi[n * (DP * DD) + i] * r;
        split1(v, H[n * (DP * DD) + i], L[n * (DP * DD) + i]);
    }
}

__global__ void softmax_row_kernel(const float* __restrict__ Lg,
                                   unsigned short* __restrict__ H, unsigned short* __restrict__ Lo) {
    const float* Lr = Lg + (size_t)blockIdx.x * DS;
    unsigned short* Hr = H + (size_t)blockIdx.x * DS;
    unsigned short* Or = Lo + (size_t)blockIdx.x * DS;
    int t = threadIdx.x;
    float v[4]; float mx = -1e30f;
#pragma unroll
    for (int j = 0; j < 4; j++) { v[j] = Lr[t + j * 256]; mx = fmaxf(mx, v[j]); }
    __shared__ float sd[256];
    sd[t] = mx; __syncthreads();
    for (int off = 128; off > 0; off >>= 1) { if (t < off) sd[t] = fmaxf(sd[t], sd[t + off]); __syncthreads(); }
    mx = sd[0]; __syncthreads();
    float sum = 0.f;
#pragma unroll
    for (int j = 0; j < 4; j++) { v[j] = expf(v[j] - mx); sum += v[j]; }
    sd[t] = sum; __syncthreads();
    for (int off = 128; off > 0; off >>= 1) { if (t < off) sd[t] += sd[t + off]; __syncthreads(); }
    float inv = 1.f / sd[0];
#pragma unroll
    for (int j = 0; j < 4; j++) {
        unsigned short hh, ll;
        split1(v[j] * inv, hh, ll);
        Hr[t + j * 256] = hh; Or[t + j * 256] = ll;
    }
}

// 512 threads: (32, 16)
__global__ void softmax_col_kernel(const float* __restrict__ Lg,
                                   unsigned short* __restrict__ H, unsigned short* __restrict__ Lo) {
    int b = blockIdx.y;
    int s = blockIdx.x * 32 + threadIdx.x;
    int ty = threadIdx.y;
    const float* Lb = Lg + (size_t)b * DM * DS;
    unsigned short* Hb = H + (size_t)b * DM * DS;
    unsigned short* Ob = Lo + (size_t)b * DM * DS;
    __shared__ float red[16][32];
    float mx = -1e30f;
    for (int m = ty; m < DM; m += 16) mx = fmaxf(mx, Lb[(size_t)m * DS + s]);
    red[ty][threadIdx.x] = mx; __syncthreads();
    if (ty == 0) {
        float v = red[0][threadIdx.x];
#pragma unroll
        for (int i = 1; i < 16; i++) v = fmaxf(v, red[i][threadIdx.x]);
        red[0][threadIdx.x] = v;
    }
    __syncthreads();
    mx = red[0][threadIdx.x]; __syncthreads();
    float sum = 0.f;
    for (int m = ty; m < DM; m += 16) sum += expf(Lb[(size_t)m * DS + s] - mx);
    red[ty][threadIdx.x] = sum; __syncthreads();
    if (ty == 0) {
        float v = 0.f;
#pragma unroll
        for (int i = 0; i < 16; i++) v += red[i][threadIdx.x];
        red[0][threadIdx.x] = v;
    }
    __syncthreads();
    float inv = 1.f / red[0][threadIdx.x];
    for (int m = ty; m < DM; m += 16) {
        unsigned short hh, ll;
        split1(expf(Lb[(size_t)m * DS + s] - mx) * inv, hh, ll);
        Hb[(size_t)m * DS + s] = hh; Ob[(size_t)m * DS + s] = ll;
    }
}

// LayerNorm: read Xs [b][n*16+p][d], write LN planes [n][b*16+p][d]
__global__ void layernorm_kernel(const float* __restrict__ X,
                                 unsigned short* __restrict__ H, unsigned short* __restrict__ L,
                                 const float* __restrict__ g, const float* __restrict__ bb) {
    int row = blockIdx.x;
    int b = row >> 10;
    int slot = row & 1023;
    int n = slot >> 4;
    int p = slot & 15;
    const float* Xr = X + (size_t)row * DD;
    size_t obase = ((size_t)n * 128 + b * 16 + p) * DD;
    __shared__ float sh[DD];
    __shared__ float red[256];
    int t = threadIdx.x;
    float ls = 0.f;
    for (int j = t; j < DD; j += 256) { float v = Xr[j]; sh[j] = v; ls += v; }
    red[t] = ls; __syncthreads();
    for (int off = 128; off > 0; off >>= 1) { if (t < off) red[t] += red[t + off]; __syncthreads(); }
    float mu = red[0] * (1.0f / DD); __syncthreads();
    float lv = 0.f;
    for (int j = t; j < DD; j += 256) { float dv = sh[j] - mu; lv += dv * dv; }
    red[t] = lv; __syncthreads();
    for (int off = 128; off > 0; off >>= 1) { if (t < off) red[t] += red[t + off]; __syncthreads(); }
    float is = rsqrtf(red[0] * (1.0f / DD) + 1e-5f); __syncthreads();
    for (int j = t; j < DD; j += 256) {
        float v = (sh[j] - mu) * is * g[n * DD + j] + bb[n * DD + j];
        unsigned short hh, ll;
        split1(v, hh, ll);
        H[obase + j] = hh; L[obase + j] = ll;
    }
}

// ================= mma.sync GEMM =================
// 512 threads, 16 warps 4x4; warp tile 32x32; CTA tile 128x128; kc=64.
// PA/PB: operand pre-split bf16 planes (1) or fp32 convert-in-kernel (0)
// TA/TB: 0 = row-major [row][K], 1 = K-major [K][row]
// EPI: 0 none, 1 +bias, 2 +bias+gelu ; CSC: scattered rows ; OSPLIT: out to bf16 planes
template <int PA, int TA, int PB, int TB, int EPI, int CSC, int OSPLIT>
__global__ void __launch_bounds__(512)
gemm_mma(const unsigned short* __restrict__ Ah, const unsigned short* __restrict__ Al,
         const float* __restrict__ Af,
         const unsigned short* __restrict__ Bh, const unsigned short* __restrict__ Bl,
         const float* __restrict__ Bf,
         unsigned short* __restrict__ Ph, unsigned short* __restrict__ Pl,
         float* __restrict__ Cf, const float* __restrict__ bias,
         int K, int lda, int ldb, int ldc,
         long long aBS, long long bBS, long long cBS, int biasBS, long long c_sb) {
    constexpr int ASZ = TA ? 64 * 272 : 128 * 144;
    constexpr int BSZ = TB ? 64 * 272 : 128 * 144;
    constexpr int STAGE = 2 * ASZ + 2 * BSZ;
    extern __shared__ char smem[];
    const uint32_t sm0 = smem_to_u32(smem);

    const int tid = threadIdx.x;
    const int l = tid & 31;
    const int wid = tid >> 5;
    const int wm = wid & 3;
    const int wn = wid >> 2;
    const int z = blockIdx.z;
    const int bm = blockIdx.y * 128;
    const int bn = blockIdx.x * 128;
    const int NC = K >> 6;

    const unsigned short* Ahb = nullptr; const unsigned short* Alb = nullptr;
    const float* Afb = nullptr;
    if (PA) {
        Ahb = Ah + z * aBS + (TA ? (size_t)bm : (size_t)bm * lda);
        Alb = Al + z * aBS + (TA ? (size_t)bm : (size_t)bm * lda);
    } else {
        Afb = Af + z * aBS + (TA ? (size_t)bm : (size_t)bm * lda);
    }
    const unsigned short* Bhb = nullptr; const unsigned short* Blb = nullptr;
    const float* Bfb = nullptr;
    if (PB) {
        Bhb = Bh + z * bBS + (TB ? (size_t)bn : (size_t)bn * ldb);
        Blb = Bl + z * bBS + (TB ? (size_t)bn : (size_t)bn * ldb);
    } else {
        Bfb = Bf + z * bBS + (TB ? (size_t)bn : (size_t)bn * ldb);
    }

    uint4 rah[2], ral[2]; float4 raf[4];
    uint4 rbh[2], rbl[2]; float4 rbf[4];

    auto LDG = [&](int c) {
        int k0 = c * 64;
        if (PA) {
#pragma unroll
            for (int i = 0; i < 2; i++) {
                int idx = tid + i * 512;
                size_t off;
                if (!TA) { int row = idx >> 3, cg = idx & 7; off = (size_t)row * lda + k0 + cg * 8; }
                else     { int kk = idx >> 4, cg = idx & 15; off = (size_t)(k0 + kk) * lda + cg * 8; }
                rah[i] = *(const uint4*)(Ahb + off);
                ral[i] = *(const uint4*)(Alb + off);
            }
        } else {
#pragma unroll
            for (int i = 0; i < 4; i++) {
                int idx = tid + i * 512;
                size_t off;
                if (!TA) { int row = idx >> 4, cg = idx & 15; off = (size_t)row * lda + k0 + cg * 4; }
                else     { int kk = idx >> 5, cg = idx & 31; off = (size_t)(k0 + kk) * lda + cg * 4; }
                raf[i] = *(const float4*)(Afb + off);
            }
        }
        if (PB) {
#pragma unroll
            for (int i = 0; i < 2; i++) {
                int idx = tid + i * 512;
                size_t off;
                if (!TB) { int row = idx >> 3, cg = idx & 7; off = (size_t)row * ldb + k0 + cg * 8; }
                else     { int kk = idx >> 4, cg = idx & 15; off = (size_t)(k0 + kk) * ldb + cg * 8; }
                rbh[i] = *(const uint4*)(Bhb + off);
                rbl[i] = *(const uint4*)(Blb + off);
            }
        } else {
#pragma unroll
            for (int i = 0; i < 4; i++) {
                int idx = tid + i * 512;
                size_t off;
                if (!TB) { int row = idx >> 4, cg = idx & 15; off = (size_t)row * ldb + k0 + cg * 4; }
                else     { int kk = idx >> 5, cg = idx & 31; off = (size_t)(k0 + kk) * ldb + cg * 4; }
                rbf[i] = *(const float4*)(Bfb + off);
            }
        }
    };

    auto STS = [&](int s) {
        char* st = smem + s * STAGE;
        char* ah = st;
        char* al = st + ASZ;
        char* bh = st + 2 * ASZ;
        char* bl = st + 2 * ASZ + BSZ;
        if (PA) {
#pragma unroll
            for (int i = 0; i < 2; i++) {
                int idx = tid + i * 512;
                int so = (!TA) ? ((idx >> 3) * 144 + (idx & 7) * 16)
                               : ((idx >> 4) * 272 + (idx & 15) * 16);
                *(uint4*)(ah + so) = rah[i];
                *(uint4*)(al + so) = ral[i];
            }
        } else {
#pragma unroll
            for (int i = 0; i < 4; i++) {
                int idx = tid + i * 512;
                int so = (!TA) ? ((idx >> 4) * 144 + (idx & 15) * 8)
                               : ((idx >> 5) * 272 + (idx & 31) * 8);
                uint32_t h01, h23, l01, l23;
                split4(raf[i], h01, h23, l01, l23);
                *(uint2*)(ah + so) = make_uint2(h01, h23);
                *(uint2*)(al + so) = make_uint2(l01, l23);
            }
        }
        if (PB) {
#pragma unroll
            for (int i = 0; i < 2; i++) {
                int idx = tid + i * 512;
                int so = (!TB) ? ((idx >> 3) * 144 + (idx & 7) * 16)
                               : ((idx >> 4) * 272 + (idx & 15) * 16);
                *(uint4*)(bh + so) = rbh[i];
                *(uint4*)(bl + so) = rbl[i];
            }
        } else {
#pragma unroll
            for (int i = 0; i < 4; i++) {
                int idx = tid + i * 512;
                int so = (!TB) ? ((idx >> 4) * 144 + (idx & 15) * 8)
                               : ((idx >> 5) * 272 + (idx & 31) * 8);
                uint32_t h01, h23, l01, l23;
                split4(rbf[i], h01, h23, l01, l23);
                *(uint2*)(bh + so) = make_uint2(h01, h23);
                *(uint2*)(bl + so) = make_uint2(l01, l23);
            }
        }
    };

    float acc[2][4][4];
#pragma unroll
    for (int mt = 0; mt < 2; mt++)
#pragma unroll
        for (int nt = 0; nt < 4; nt++)
#pragma unroll
            for (int q = 0; q < 4; q++) acc[mt][nt][q] = 0.f;

    auto COMPUTE = [&](int s) {
        uint32_t sbA = sm0 + s * STAGE;
        uint32_t sbB = sbA + 2 * ASZ;
#pragma unroll
        for (int ks = 0; ks < 4; ks++) {
            uint32_t ahi[2][4], alo[2][4];
#pragma unroll
            for (int mt = 0; mt < 2; mt++) {
                int mr = wm * 32 + mt * 16;
                if (TA) {
                    int krow = ks * 16 + (l & 7) + ((l >> 4) << 3);
                    int col = mr + (((l >> 3) & 1) << 3);
                    uint32_t addr = sbA + krow * 272 + col * 2;
                    ldsm_x4_t(ahi[mt], addr);
                    ldsm_x4_t(alo[mt], addr + ASZ);
                } else {
                    int row = mr + (l & 15);
                    uint32_t addr = sbA + row * 144 + ks * 32 + ((l >> 4) & 1) * 16;
                    ldsm_x4(ahi[mt], addr);
                    ldsm_x4(alo[mt], addr + ASZ);
                }
            }
#pragma unroll
            for (int np = 0; np < 2; np++) {
                int nr = wn * 32 + np * 16;
                uint32_t bhi[4], blo[4];
                if (TB) {
                    int krow = ks * 16 + (l & 7) + (((l >> 3) & 1) << 3);
                    int col = nr + ((l >> 4) << 3);
                    uint32_t addr = sbB + krow * 272 + col * 2;
                    ldsm_x4_t(bhi, addr);
                    ldsm_x4_t(blo, addr + BSZ);
                } else {
                    int row = nr + (l & 7) + ((l >> 4) << 3);
                    uint32_t addr = sbB + row * 144 + ks * 32 + (((l >> 3) & 1) << 4);
                    ldsm_x4(bhi, addr);
                    ldsm_x4(blo, addr + BSZ);
                }
#pragma unroll
                for (int half = 0; half < 2; half++) {
                    int nt = np * 2 + half;
#pragma unroll
                    for (int mt = 0; mt < 2; mt++) {
                        mma_bf16(acc[mt][nt], ahi[mt], bhi + 2 * half);
                        mma_bf16(acc[mt][nt], alo[mt], bhi + 2 * half);
                        mma_bf16(acc[mt][nt], ahi[mt], blo + 2 * half);
                    }
                }
            }
        }
    };

    LDG(0);
    STS(0);
    if (NC > 1) LDG(1);
    __syncthreads();
    for (int c = 0; c < NC; c++) {
        if (c + 1 < NC) STS((c + 1) & 1);
        if (c + 2 < NC) LDG(c + 2);
        COMPUTE(c & 1);
        __syncthreads();
    }

    // ---------------- epilogue via smem staging ----------------
    float* Cs = (float*)smem;   // [128][132]
#pragma unroll
    for (int mt = 0; mt < 2; mt++) {
#pragma unroll
        for (int nt = 0; nt < 4; nt++) {
            int r0 = wm * 32 + mt * 16 + (l >> 2);
            int c0 = wn * 32 + nt * 8 + (l & 3) * 2;
            Cs[r0 * 132 + c0] = acc[mt][nt][0];
            Cs[r0 * 132 + c0 + 1] = acc[mt][nt][1];
            Cs[(r0 + 8) * 132 + c0] = acc[mt][nt][2];
            Cs[(r0 + 8) * 132 + c0 + 1] = acc[mt][nt][3];
        }
    }
    __syncthreads();
    const float* bp = (EPI >= 1) ? (bias + (size_t)z * biasBS + bn) : nullptr;
    if (OSPLIT) {
#pragma unroll 4
        for (int i = 0; i < 16; i++) {
            int pidx = i * 512 + tid;          // 8192 pairs
            int r = pidx >> 6;
            int c2 = (pidx & 63) * 2;
            float v0 = Cs[r * 132 + c2];
            float v1 = Cs[r * 132 + c2 + 1];
            if (EPI >= 1) { v0 += __ldg(bp + c2); v1 += __ldg(bp + c2 + 1); }
            if (EPI == 2) {
                v0 = 0.5f * v0 * (1.0f + erff(v0 * 0.70710678118654752440f));
                v1 = 0.5f * v1 * (1.0f + erff(v1 * 0.70710678118654752440f));
            }
            uint32_t u0 = __float_as_uint(v0), u1 = __float_as_uint(v1);
            uint32_t hp = __byte_perm(u0, u1, 0x7632);
            float h0 = __uint_as_float(u0 & 0xFFFF0000u);
            float h1 = __uint_as_float(u1 & 0xFFFF0000u);
            uint32_t lp;
            asm("cvt.rn.bf16x2.f32 %0, %1, %2;" : "=r"(lp) : "f"(v1 - h1), "f"(v0 - h0));
            size_t off;
            if (CSC)
                off = (size_t)z * cBS + (size_t)(r >> 4) * c_sb + (size_t)(r & 15) * ldc + bn + c2;
            else
                off = (size_t)z * cBS + (size_t)(bm + r) * ldc + bn + c2;
            *(uint32_t*)(Ph + off) = hp;
            *(uint32_t*)(Pl + off) = lp;
        }
    } else {
#pragma unroll 4
        for (int i = 0; i < 32; i++) {
            int idx = i * 512 + tid;
            int r = idx >> 7, cc = idx & 127;
            float v = Cs[r * 132 + cc];
            if (EPI >= 1) v += __ldg(bp + cc);
            if (EPI == 2) v = 0.5f * v * (1.0f + erff(v * 0.70710678118654752440f));
            size_t off;
            if (CSC)
                off = (size_t)z * cBS + (size_t)(r >> 4) * c_sb + (size_t)(r & 15) * ldc + bn + cc;
            else
                off = (size_t)z * cBS + (size_t)(bm + r) * ldc + bn + cc;
            Cf[off] = v;
        }
    }
}

// ================= host launcher =================
extern "C" void kernel_launch(void* const* d_in, const int* in_sizes, int n_in,
                              void* d_out, int out_size) {
    const float* x    = (const float*)d_in[0];
    const float* phi  = (const float*)d_in[1];
    const float* ln_g = (const float*)d_in[2];
    const float* ln_b = (const float*)d_in[3];
    const float* w1   = (const float*)d_in[4];
    const float* b1   = (const float*)d_in[5];
    const float* w2   = (const float*)d_in[6];
    const float* b2   = (const float*)d_in[7];
    float* out = (float*)d_out;

    float *logits, *Xs;
    unsigned short *xh, *xl, *ph, *pl, *Ch, *Cl, *Dh, *Dl, *LNh, *LNl, *hh, *hl, *Yh, *Yl;
    cudaGetSymbolAddress((void**)&logits, g_logits);
    cudaGetSymbolAddress((void**)&Xs, g_Xs);
    cudaGetSymbolAddress((void**)&xh, g_xh);   cudaGetSymbolAddress((void**)&xl, g_xl);
    cudaGetSymbolAddress((void**)&ph, g_ph);   cudaGetSymbolAddress((void**)&pl, g_pl);
    cudaGetSymbolAddress((void**)&Ch, g_Ch);   cudaGetSymbolAddress((void**)&Cl, g_Cl);
    cudaGetSymbolAddress((void**)&Dh, g_Dh);   cudaGetSymbolAddress((void**)&Dl, g_Dl);
    cudaGetSymbolAddress((void**)&LNh, g_LNh); cudaGetSymbolAddress((void**)&LNl, g_LNl);
    cudaGetSymbolAddress((void**)&hh, g_hh);   cudaGetSymbolAddress((void**)&hl, g_hl);
    cudaGetSymbolAddress((void**)&Yh, g_Yh);   cudaGetSymbolAddress((void**)&Yl, g_Yl);

    // smem per instantiation (double-buffered stage)
    const int SM_G2 = 2 * (2 * 128 * 144 + 2 * 128 * 144);   // 147456
    const int SM_G4 = 2 * (2 * 64 * 272 + 2 * 64 * 272);     // 139264
    const int SM_G678 = 2 * (2 * 128 * 144 + 2 * 64 * 272);  // 143360
    cudaFuncSetAttribute((const void*)gemm_mma<1,0,1,0,0,0,0>, cudaFuncAttributeMaxDynamicSharedMemorySize, SM_G2);
    cudaFuncSetAttribute((const void*)gemm_mma<1,1,1,1,0,0,0>, cudaFuncAttributeMaxDynamicSharedMemorySize, SM_G4);
    cudaFuncSetAttribute((const void*)gemm_mma<1,0,0,1,2,0,1>, cudaFuncAttributeMaxDynamicSharedMemorySize, SM_G678);
    cudaFuncSetAttribute((const void*)gemm_mma<1,0,0,1,1,1,1>, cudaFuncAttributeMaxDynamicSharedMemorySize, SM_G678);
    cudaFuncSetAttribute((const void*)gemm_mma<1,0,1,1,0,0,0>, cudaFuncAttributeMaxDynamicSharedMemorySize, SM_G678);

    // 0. split x
    convert_split_kernel<<<(DB * DM * DD / 4 + 255) / 256, 256>>>(x, xh, xl, DB * DM * DD / 4);

    // 1. normalize + split phi
    phi_norm_kernel<<<(DP * DD + 255) / 256, 256>>>(phi, ph, pl);

    // 2. logits = x @ phin^T   (A=x planes row-major, B=phin planes row-major)
    gemm_mma<1,0,1,0,0,0,0><<<dim3(DS / 128, (DB * DM) / 128, 1), 512, SM_G2>>>(
        xh, xl, nullptr, ph, pl, nullptr, nullptr, nullptr, logits, nullptr,
        DD, DD, DD, DS, 0, 0, 0, 0, 0);

    // 3. softmaxes -> C,D planes
    softmax_row_kernel<<<DB * DM, 256>>>(logits, Ch, Cl);
    softmax_col_kernel<<<dim3(DS / 32, DB), dim3(32, 16)>>>(logits, Dh, Dl);

    // 4. Xs = D^T @ x   (A=D planes K-major, B=x planes K-major), fp32 out
    gemm_mma<1,1,1,1,0,0,0><<<dim3(DD / 128, DS / 128, DB), 512, SM_G4>>>(
        Dh, Dl, nullptr, xh, xl, nullptr, nullptr, nullptr, Xs, nullptr,
        DM, DS, DD, DD,
        (long long)DM * DS, (long long)DM * DD, (long long)DS * DD, 0, 0);

    // 5. LayerNorm -> LN planes (expert layout)
    layernorm_kernel<<<DB * DS, 256>>>(Xs, LNh, LNl, ln_g, ln_b);

    // 6. hdn = LN @ w1 + b1, GELU  (A planes row-major, B fp32 K-major), split out
    gemm_mma<1,0,0,1,2,0,1><<<dim3(DH / 128, 1, DN), 512, SM_G678>>>(
        LNh, LNl, nullptr, nullptr, nullptr, w1, hh, hl, nullptr, b1,
        DD, DD, DH, DH,
        (long long)128 * DD, (long long)DD * DH, (long long)128 * DH, DH, 0);

    // 7. Ys = hdn @ w2 + b2  (A planes row-major, B fp32 K-major), split out, scattered
    gemm_mma<1,0,0,1,1,1,1><<<dim3(DD / 128, 1, DN), 512, SM_G678>>>(
        hh, hl, nullptr, nullptr, nullptr, w2, Yh, Yl, nullptr, b2,
        DH, DH, DD, DD,
        (long long)128 * DH, (long long)DH * DD, (long long)DP * DD, DD,
        (long long)DS * DD);

    // 8. Y = C @ Ys  (A=C planes row-major, B=Ys planes K-major), fp32 out
    gemm_mma<1,0,1,1,0,0,0><<<dim3(DD / 128, DM / 128, DB), 512, SM_G678>>>(
        Ch, Cl, nullptr, Yh, Yl, nullptr, nullptr, nullptr, out, nullptr,
        DS, DS, DD, DD,
        (long long)DM * DS, (long long)DS * DD, (long long)DM * DD, 0, 0);
}

// round 7
// speedup vs baseline: 1.4349x; 1.4349x over previous
#include <cuda_runtime.h>
#include <cuda_bf16.h>
#include <math.h>
#include <cstdint>

// ---------------- dimensions ----------------
#define DB 8
#define DM 1024
#define DD 768
#define DN 64
#define DP 16
#define DH 1536
#define DS 1024   // n*p

// ---------------- scratch ----------------
__device__ float g_phin[DN * DP * DD];
__device__ float g_logits[DB * DM * DS];
__device__ float g_D[DB * DM * DS];
__device__ float g_C[DB * DM * DS];
__device__ float g_Xs[DB * DS * DD];
__device__ float g_LN[DN * DB * DP * DD];       // [n][b*16+p][d]
__device__ float g_hdn[DN * (DB * DP) * DH];    // [n][128][h]
__device__ float g_Ys[DB * DS * DD];            // [b][s][d]

// ================= helpers =================
__device__ __forceinline__ uint32_t smem_to_u32(const void* p) {
    uint32_t a;
    asm("{ .reg .u64 t; cvta.to.shared.u64 t, %1; cvt.u32.u64 %0, t; }" : "=r"(a) : "l"(p));
    return a;
}

// fast split: hi = truncate-to-bf16 (bit mask), lo = rn(x - hi)
__device__ __forceinline__ void split4(float4 v, uint32_t& h01, uint32_t& h23,
                                       uint32_t& l01, uint32_t& l23) {
    uint32_t ux = __float_as_uint(v.x), uy = __float_as_uint(v.y);
    uint32_t uz = __float_as_uint(v.z), uw = __float_as_uint(v.w);
    h01 = __byte_perm(ux, uy, 0x7632);
    h23 = __byte_perm(uz, uw, 0x7632);
    float hx = __uint_as_float(ux & 0xFFFF0000u);
    float hy = __uint_as_float(uy & 0xFFFF0000u);
    float hz = __uint_as_float(uz & 0xFFFF0000u);
    float hw = __uint_as_float(uw & 0xFFFF0000u);
    asm("cvt.rn.bf16x2.f32 %0, %1, %2;" : "=r"(l01) : "f"(v.y - hy), "f"(v.x - hx));
    asm("cvt.rn.bf16x2.f32 %0, %1, %2;" : "=r"(l23) : "f"(v.w - hw), "f"(v.z - hz));
}

__device__ __forceinline__ void ldsm_x4(uint32_t* r, uint32_t addr) {
    asm volatile("ldmatrix.sync.aligned.m8n8.x4.shared.b16 {%0,%1,%2,%3}, [%4];"
                 : "=r"(r[0]), "=r"(r[1]), "=r"(r[2]), "=r"(r[3]) : "r"(addr));
}
__device__ __forceinline__ void ldsm_x4_t(uint32_t* r, uint32_t addr) {
    asm volatile("ldmatrix.sync.aligned.m8n8.x4.trans.shared.b16 {%0,%1,%2,%3}, [%4];"
                 : "=r"(r[0]), "=r"(r[1]), "=r"(r[2]), "=r"(r[3]) : "r"(addr));
}
__device__ __forceinline__ void mma_bf16(float* d, const uint32_t* a, const uint32_t* b) {
    asm volatile(
        "mma.sync.aligned.m16n8k16.row.col.f32.bf16.bf16.f32 "
        "{%0,%1,%2,%3}, {%4,%5,%6,%7}, {%8,%9}, {%0,%1,%2,%3};"
        : "+f"(d[0]), "+f"(d[1]), "+f"(d[2]), "+f"(d[3])
        : "r"(a[0]), "r"(a[1]), "r"(a[2]), "r"(a[3]), "r"(b[0]), "r"(b[1]));
}

// ================= elementwise kernels =================
__global__ void phi_norm_kernel(const float* __restrict__ phi, float* __restrict__ phin) {
    int i = blockIdx.x * blockDim.x + threadIdx.x;
    if (i >= DP * DD) return;
    float s = 0.f;
#pragma unroll 4
    for (int n = 0; n < DN; n++) { float v = phi[n * (DP * DD) + i]; s += v * v; }
    float r = rsqrtf(s + 1e-6f);
#pragma unroll 4
    for (int n = 0; n < DN; n++) phin[n * (DP * DD) + i] = phi[n * (DP * DD) + i] * r;
}

__global__ void softmax_row_kernel(const float* __restrict__ L, float* __restrict__ O) {
    const float* Lr = L + (size_t)blockIdx.x * DS;
    float* Or = O + (size_t)blockIdx.x * DS;
    int t = threadIdx.x;
    float v[4]; float mx = -1e30f;
#pragma unroll
    for (int j = 0; j < 4; j++) { v[j] = Lr[t + j * 256]; mx = fmaxf(mx, v[j]); }
    __shared__ float sd[256];
    sd[t] = mx; __syncthreads();
    for (int off = 128; off > 0; off >>= 1) { if (t < off) sd[t] = fmaxf(sd[t], sd[t + off]); __syncthreads(); }
    mx = sd[0]; __syncthreads();
    float sum = 0.f;
#pragma unroll
    for (int j = 0; j < 4; j++) { v[j] = expf(v[j] - mx); sum += v[j]; }
    sd[t] = sum; __syncthreads();
    for (int off = 128; off > 0; off >>= 1) { if (t < off) sd[t] += sd[t + off]; __syncthreads(); }
    float inv = 1.f / sd[0];
#pragma unroll
    for (int j = 0; j < 4; j++) Or[t + j * 256] = v[j] * inv;
}

// 512 threads: (32, 16)
__global__ void softmax_col_kernel(const float* __restrict__ L, float* __restrict__ O) {
    int b = blockIdx.y;
    int s = blockIdx.x * 32 + threadIdx.x;
    int ty = threadIdx.y;   // 0..15
    const float* Lb = L + (size_t)b * DM * DS;
    float* Ob = O + (size_t)b * DM * DS;
    __shared__ float red[16][32];
    float mx = -1e30f;
    for (int m = ty; m < DM; m += 16) mx = fmaxf(mx, Lb[(size_t)m * DS + s]);
    red[ty][threadIdx.x] = mx; __syncthreads();
    if (ty == 0) {
        float v = red[0][threadIdx.x];
#pragma unroll
        for (int i = 1; i < 16; i++) v = fmaxf(v, red[i][threadIdx.x]);
        red[0][threadIdx.x] = v;
    }
    __syncthreads();
    mx = red[0][threadIdx.x]; __syncthreads();
    float sum = 0.f;
    for (int m = ty; m < DM; m += 16) sum += expf(Lb[(size_t)m * DS + s] - mx);
    red[ty][threadIdx.x] = sum; __syncthreads();
    if (ty == 0) {
        float v = 0.f;
#pragma unroll
        for (int i = 0; i < 16; i++) v += red[i][threadIdx.x];
        red[0][threadIdx.x] = v;
    }
    __syncthreads();
    float inv = 1.f / red[0][threadIdx.x];
    for (int m = ty; m < DM; m += 16)
        Ob[(size_t)m * DS + s] = expf(Lb[(size_t)m * DS + s] - mx) * inv;
}

// LayerNorm: read Xs [b][n*16+p][d], write LN [n][b*16+p][d]
__global__ void layernorm_kernel(const float* __restrict__ X, float* __restrict__ Yo,
                                 const float* __restrict__ g, const float* __restrict__ bb) {
    int row = blockIdx.x;
    int b = row >> 10;
    int slot = row & 1023;
    int n = slot >> 4;
    int p = slot & 15;
    const float* Xr = X + (size_t)row * DD;
    float* Yr = Yo + ((size_t)n * 128 + b * 16 + p) * DD;
    __shared__ float sh[DD];
    __shared__ float red[256];
    int t = threadIdx.x;
    float ls = 0.f;
    for (int j = t; j < DD; j += 256) { float v = Xr[j]; sh[j] = v; ls += v; }
    red[t] = ls; __syncthreads();
    for (int off = 128; off > 0; off >>= 1) { if (t < off) red[t] += red[t + off]; __syncthreads(); }
    float mu = red[0] * (1.0f / DD); __syncthreads();
    float lv = 0.f;
    for (int j = t; j < DD; j += 256) { float dv = sh[j] - mu; lv += dv * dv; }
    red[t] = lv; __syncthreads();
    for (int off = 128; off > 0; off >>= 1) { if (t < off) red[t] += red[t + off]; __syncthreads(); }
    float is = rsqrtf(red[0] * (1.0f / DD) + 1e-5f); __syncthreads();
    for (int j = t; j < DD; j += 256)
        Yr[j] = (sh[j] - mu) * is * g[n * DD + j] + bb[n * DD + j];
}

// ================= mma.sync GEMM =================
// 512 threads, 16 warps in 4x4 grid; warp tile 32x32; CTA tile 128x128, kc=32.
// 3-term bf16 split, THREE-stage smem pipeline, ONE sync/iter.
// TA/TB: 0 = row-major [row][K], 1 = K-major [K][row]
// EPI: 0 none, 1 +bias, 2 +bias+gelu ; CSC: 1 = scattered output rows
template <int TA, int TB, int EPI, int CSC>
__global__ void __launch_bounds__(512)
gemm_mma(const float* __restrict__ A, const float* __restrict__ B,
         float* __restrict__ C, const float* __restrict__ bias,
         int K, int lda, int ldb, int ldc,
         long long aBS, long long bBS, long long cBS, int biasBS, long long c_sb) {
    constexpr int ASZ1 = TA ? 32 * 272 : 128 * 80;
    constexpr int BSZ1 = TB ? 32 * 272 : 128 * 80;
    constexpr int STAGE = 2 * ASZ1 + 2 * BSZ1;
    extern __shared__ char smem[];
    const uint32_t sm0 = smem_to_u32(smem);

    const int tid = threadIdx.x;
    const int l = tid & 31;
    const int wid = tid >> 5;       // 0..15
    const int wm = wid & 3;         // 4 M groups of 32 rows
    const int wn = wid >> 2;        // 4 N groups of 32 cols
    const int z = blockIdx.z;
    const int bm = blockIdx.y * 128;
    const int bn = blockIdx.x * 128;
    const int NC = K >> 5;

    const float* Ab = A + (size_t)z * aBS + (TA ? (size_t)bm : (size_t)bm * lda);
    const float* Bb = B + (size_t)z * bBS + (TB ? (size_t)bn : (size_t)bn * ldb);

    float4 ra[2], rb[2];

    auto LDG = [&](int c) {
        int k0 = c * 32;
#pragma unroll
        for (int i = 0; i < 2; i++) {
            int p = tid + i * 512;
            if (TA) ra[i] = *(const float4*)(Ab + (size_t)(k0 + (p >> 5)) * lda + (p & 31) * 4);
            else    ra[i] = *(const float4*)(Ab + (size_t)(p >> 3) * lda + k0 + (p & 7) * 4);
            if (TB) rb[i] = *(const float4*)(Bb + (size_t)(k0 + (p >> 5)) * ldb + (p & 31) * 4);
            else    rb[i] = *(const float4*)(Bb + (size_t)(p >> 3) * ldb + k0 + (p & 7) * 4);
        }
    };

    auto STS = [&](int s) {
        char* st = smem + s * STAGE;
        char* ahis = st;
        char* alos = st + ASZ1;
        char* bhis = st + 2 * ASZ1;
        char* blos = st + 2 * ASZ1 + BSZ1;
#pragma unroll
        for (int i = 0; i < 2; i++) {
            int p = tid + i * 512;
            int aoff = TA ? ((p >> 5) * 272 + (p & 31) * 8) : ((p >> 3) * 80 + (p & 7) * 8);
            int boff = TB ? ((p >> 5) * 272 + (p & 31) * 8) : ((p >> 3) * 80 + (p & 7) * 8);
            uint32_t h01, h23, l01, l23;
            split4(ra[i], h01, h23, l01, l23);
            *(uint2*)(ahis + aoff) = make_uint2(h01, h23);
            *(uint2*)(alos + aoff) = make_uint2(l01, l23);
            split4(rb[i], h01, h23, l01, l23);
            *(uint2*)(bhis + boff) = make_uint2(h01, h23);
            *(uint2*)(blos + boff) = make_uint2(l01, l23);
        }
    };

    float acc[2][4][4];
#pragma unroll
    for (int mt = 0; mt < 2; mt++)
#pragma unroll
        for (int nt = 0; nt < 4; nt++)
#pragma unroll
            for (int q = 0; q < 4; q++) acc[mt][nt][q] = 0.f;

    auto COMPUTE = [&](int s) {
        uint32_t sbA = sm0 + s * STAGE;
        uint32_t sbB = sbA + 2 * ASZ1;
#pragma unroll
        for (int ks = 0; ks < 2; ks++) {
            uint32_t ahi[2][4], alo[2][4];
#pragma unroll
            for (int mt = 0; mt < 2; mt++) {
                int mr = wm * 32 + mt * 16;
                if (TA) {
                    int krow = ks * 16 + (l & 7) + ((l >> 4) << 3);
                    int col = mr + (((l >> 3) & 1) << 3);
                    uint32_t addr = sbA + krow * 272 + col * 2;
                    ldsm_x4_t(ahi[mt], addr);
                    ldsm_x4_t(alo[mt], addr + ASZ1);
                } else {
                    int row = mr + (l & 15);
                    uint32_t addr = sbA + row * 80 + ks * 32 + ((l >> 4) & 1) * 16;
                    ldsm_x4(ahi[mt], addr);
                    ldsm_x4(alo[mt], addr + ASZ1);
                }
            }
#pragma unroll
            for (int np = 0; np < 2; np++) {
                int nr = wn * 32 + np * 16;
                uint32_t bhi[4], blo[4];
                if (TB) {
                    int krow = ks * 16 + (l & 7) + (((l >> 3) & 1) << 3);
                    int col = nr + ((l >> 4) << 3);
                    uint32_t addr = sbB + krow * 272 + col * 2;
                    ldsm_x4_t(bhi, addr);
                    ldsm_x4_t(blo, addr + BSZ1);
                } else {
                    int row = nr + (l & 7) + ((l >> 4) << 3);
                    uint32_t addr = sbB + row * 80 + ks * 32 + (((l >> 3) & 1) << 4);
                    ldsm_x4(bhi, addr);
                    ldsm_x4(blo, addr + BSZ1);
                }
#pragma unroll
                for (int half = 0; half < 2; half++) {
                    int nt = np * 2 + half;
#pragma unroll
                    for (int mt = 0; mt < 2; mt++) {
                        mma_bf16(acc[mt][nt], ahi[mt], bhi + 2 * half);
                        mma_bf16(acc[mt][nt], alo[mt], bhi + 2 * half);
                        mma_bf16(acc[mt][nt], ahi[mt], blo + 2 * half);
                    }
                }
            }
        }
    };

    // 3-stage pipeline: at iter c, regs hold chunk c+1; write it to stage (c+1)%3,
    // prefetch chunk c+2, compute stage c%3, one barrier.
    LDG(0);
    STS(0);
    if (NC > 1) LDG(1);
    __syncthreads();
    int sc = 0;
    for (int c = 0; c < NC; c++) {
        int ss = sc + 1; if (ss == 3) ss = 0;
        if (c + 1 < NC) STS(ss);
        if (c + 2 < NC) LDG(c + 2);
        COMPUTE(sc);
        __syncthreads();
        sc = ss;
    }

    // ---------------- epilogue via smem staging ----------------
    float* Cs = (float*)smem;   // [128][132]
#pragma unroll
    for (int mt = 0; mt < 2; mt++) {
#pragma unroll
        for (int nt = 0; nt < 4; nt++) {
            int r0 = wm * 32 + mt * 16 + (l >> 2);
            int c0 = wn * 32 + nt * 8 + (l & 3) * 2;
            Cs[r0 * 132 + c0] = acc[mt][nt][0];
            Cs[r0 * 132 + c0 + 1] = acc[mt][nt][1];
            Cs[(r0 + 8) * 132 + c0] = acc[mt][nt][2];
            Cs[(r0 + 8) * 132 + c0 + 1] = acc[mt][nt][3];
        }
    }
    __syncthreads();
    const float* bp = (EPI >= 1) ? (bias + (size_t)z * biasBS + bn) : nullptr;
#pragma unroll 4
    for (int i = 0; i < 32; i++) {
        int idx = i * 512 + tid;
        int r = idx >> 7, cc = idx & 127;
        float v = Cs[r * 132 + cc];
        if (EPI >= 1) v += __ldg(bp + cc);
        if (EPI == 2) v = 0.5f * v * (1.0f + erff(v * 0.70710678118654752440f));
        size_t off;
        if (CSC)
            off = (size_t)z * cBS + (size_t)(r >> 4) * c_sb + (size_t)(r & 15) * ldc + bn + cc;
        else
            off = (size_t)z * cBS + (size_t)(bm + r) * ldc + bn + cc;
        C[off] = v;
    }
}

// ================= host launcher =================
extern "C" void kernel_launch(void* const* d_in, const int* in_sizes, int n_in,
                              void* d_out, int out_size) {
    const float* x    = (const float*)d_in[0];
    const float* phi  = (const float*)d_in[1];
    const float* ln_g = (const float*)d_in[2];
    const float* ln_b = (const float*)d_in[3];
    const float* w1   = (const float*)d_in[4];
    const float* b1   = (const float*)d_in[5];
    const float* w2   = (const float*)d_in[6];
    const float* b2   = (const float*)d_in[7];
    float* out = (float*)d_out;

    float *phin, *logits, *Dbuf, *Cbuf, *Xs, *LN, *hdn, *Ys;
    cudaGetSymbolAddress((void**)&phin, g_phin);
    cudaGetSymbolAddress((void**)&logits, g_logits);
    cudaGetSymbolAddress((void**)&Dbuf, g_D);
    cudaGetSymbolAddress((void**)&Cbuf, g_C);
    cudaGetSymbolAddress((void**)&Xs, g_Xs);
    cudaGetSymbolAddress((void**)&LN, g_LN);
    cudaGetSymbolAddress((void**)&hdn, g_hdn);
    cudaGetSymbolAddress((void**)&Ys, g_Ys);

    // 3-stage smem sizes
    const int SM00 = 3 * (2 * 128 * 80 + 2 * 128 * 80);       // 122880
    const int SM11 = 3 * (2 * 32 * 272 + 2 * 32 * 272);       // 104448
    const int SM01 = 3 * (2 * 128 * 80 + 2 * 32 * 272);       // 113664
    cudaFuncSetAttribute(gemm_mma<0,0,0,0>, cudaFuncAttributeMaxDynamicSharedMemorySize, SM00);
    cudaFuncSetAttribute(gemm_mma<1,1,0,0>, cudaFuncAttributeMaxDynamicSharedMemorySize, SM11);
    cudaFuncSetAttribute(gemm_mma<0,1,2,0>, cudaFuncAttributeMaxDynamicSharedMemorySize, SM01);
    cudaFuncSetAttribute(gemm_mma<0,1,1,1>, cudaFuncAttributeMaxDynamicSharedMemorySize, SM01);
    cudaFuncSetAttribute(gemm_mma<0,1,0,0>, cudaFuncAttributeMaxDynamicSharedMemorySize, SM01);

    // 1. normalize phi
    phi_norm_kernel<<<(DP * DD + 255) / 256, 256>>>(phi, phin);

    // 2. logits[8192,1024] = x @ phin^T
    gemm_mma<0,0,0,0><<<dim3(DS / 128, (DB * DM) / 128, 1), 512, SM00>>>(
        x, phin, logits, nullptr, DD, DD, DD, DS, 0, 0, 0, 0, 0);

    // 3. softmaxes
    softmax_row_kernel<<<DB * DM, 256>>>(logits, Cbuf);
    softmax_col_kernel<<<dim3(DS / 32, DB), dim3(32, 16)>>>(logits, Dbuf);

    // 4. Xs[b][s][d] = D_b^T @ x_b
    gemm_mma<1,1,0,0><<<dim3(DD / 128, DS / 128, DB), 512, SM11>>>(
        Dbuf, x, Xs, nullptr, DM, DS, DD, DD,
        (long long)DM * DS, (long long)DM * DD, (long long)DS * DD, 0, 0);

    // 5. LayerNorm + gather into expert layout
    layernorm_kernel<<<DB * DS, 256>>>(Xs, LN, ln_g, ln_b);

    // 6. hdn[n][128][h] = LN[n] @ w1[n] + b1, GELU
    gemm_mma<0,1,2,0><<<dim3(DH / 128, 1, DN), 512, SM01>>>(
        LN, w1, hdn, b1, DD, DD, DH, DH,
        (long long)128 * DD, (long long)DD * DH, (long long)128 * DH, DH, 0);

    // 7. Ys[b][n*16+p][d] = hdn[n] @ w2[n] + b2  (scattered C)
    gemm_mma<0,1,1,1><<<dim3(DD / 128, 1, DN), 512, SM01>>>(
        hdn, w2, Ys, b2, DH, DH, DD, DD,
        (long long)128 * DH, (long long)DH * DD, (long long)DP * DD, DD,
        (long long)DS * DD);

    // 8. Y[b][m][d] = C_b @ Ys_b
    gemm_mma<0,1,0,0><<<dim3(DD / 128, DM / 128, DB), 512, SM01>>>(
        Cbuf, Ys, out, nullptr, DS, DS, DD, DD,
        (long long)DM * DS, (long long)DS * DD, (long long)DM * DD, 0, 0);
}

// round 8
// speedup vs baseline: 1.4522x; 1.0121x over previous
#include <cuda_runtime.h>
#include <cuda_bf16.h>
#include <cuda_fp16.h>
#include <math.h>
#include <cstdint>

// ---------------- dimensions ----------------
#define DB 8
#define DM 1024
#define DD 768
#define DN 64
#define DP 16
#define DH 1536
#define DS 1024   // n*p

// ---------------- scratch ----------------
__device__ float g_phin[DN * DP * DD];
__device__ float g_logits[DB * DM * DS];
__device__ float g_D[DB * DM * DS];
__device__ float g_C[DB * DM * DS];
__device__ float g_Xs[DB * DS * DD];
__device__ float g_LN[DN * DB * DP * DD];       // [n][b*16+p][d]
__device__ float g_hdn[DN * (DB * DP) * DH];    // [n][128][h]
__device__ float g_Ys[DB * DS * DD];            // [b][s][d]

// ================= helpers =================
__device__ __forceinline__ uint32_t smem_to_u32(const void* p) {
    uint32_t a;
    asm("{ .reg .u64 t; cvta.to.shared.u64 t, %1; cvt.u32.u64 %0, t; }" : "=r"(a) : "l"(p));
    return a;
}

// fp16 2-level split: hi = rn(x), lo = rn(x - hi)
__device__ __forceinline__ void split4h(float4 v, uint32_t& h01, uint32_t& h23,
                                        uint32_t& l01, uint32_t& l23) {
    asm("cvt.rn.f16x2.f32 %0, %1, %2;" : "=r"(h01) : "f"(v.y), "f"(v.x));
    asm("cvt.rn.f16x2.f32 %0, %1, %2;" : "=r"(h23) : "f"(v.w), "f"(v.z));
    float2 f01 = __half22float2(*reinterpret_cast<__half2*>(&h01));
    float2 f23 = __half22float2(*reinterpret_cast<__half2*>(&h23));
    asm("cvt.rn.f16x2.f32 %0, %1, %2;" : "=r"(l01) : "f"(v.y - f01.y), "f"(v.x - f01.x));
    asm("cvt.rn.f16x2.f32 %0, %1, %2;" : "=r"(l23) : "f"(v.w - f23.y), "f"(v.z - f23.x));
}

// fp16 single rounding (B operand)
__device__ __forceinline__ void hi4h(float4 v, uint32_t& h01, uint32_t& h23) {
    asm("cvt.rn.f16x2.f32 %0, %1, %2;" : "=r"(h01) : "f"(v.y), "f"(v.x));
    asm("cvt.rn.f16x2.f32 %0, %1, %2;" : "=r"(h23) : "f"(v.w), "f"(v.z));
}

__device__ __forceinline__ void ldsm_x4(uint32_t* r, uint32_t addr) {
    asm volatile("ldmatrix.sync.aligned.m8n8.x4.shared.b16 {%0,%1,%2,%3}, [%4];"
                 : "=r"(r[0]), "=r"(r[1]), "=r"(r[2]), "=r"(r[3]) : "r"(addr));
}
__device__ __forceinline__ void ldsm_x4_t(uint32_t* r, uint32_t addr) {
    asm volatile("ldmatrix.sync.aligned.m8n8.x4.trans.shared.b16 {%0,%1,%2,%3}, [%4];"
                 : "=r"(r[0]), "=r"(r[1]), "=r"(r[2]), "=r"(r[3]) : "r"(addr));
}
__device__ __forceinline__ void mma_f16(float* d, const uint32_t* a, const uint32_t* b) {
    asm volatile(
        "mma.sync.aligned.m16n8k16.row.col.f32.f16.f16.f32 "
        "{%0,%1,%2,%3}, {%4,%5,%6,%7}, {%8,%9}, {%0,%1,%2,%3};"
        : "+f"(d[0]), "+f"(d[1]), "+f"(d[2]), "+f"(d[3])
        : "r"(a[0]), "r"(a[1]), "r"(a[2]), "r"(a[3]), "r"(b[0]), "r"(b[1]));
}

// ================= elementwise kernels =================
__global__ void phi_norm_kernel(const float* __restrict__ phi, float* __restrict__ phin) {
    int i = blockIdx.x * blockDim.x + threadIdx.x;
    if (i >= DP * DD) return;
    float s = 0.f;
#pragma unroll 4
    for (int n = 0; n < DN; n++) { float v = phi[n * (DP * DD) + i]; s += v * v; }
    float r = rsqrtf(s + 1e-6f);
#pragma unroll 4
    for (int n = 0; n < DN; n++) phin[n * (DP * DD) + i] = phi[n * (DP * DD) + i] * r;
}

__global__ void softmax_row_kernel(const float* __restrict__ L, float* __restrict__ O) {
    const float* Lr = L + (size_t)blockIdx.x * DS;
    float* Or = O + (size_t)blockIdx.x * DS;
    int t = threadIdx.x;
    float v[4]; float mx = -1e30f;
#pragma unroll
    for (int j = 0; j < 4; j++) { v[j] = Lr[t + j * 256]; mx = fmaxf(mx, v[j]); }
    __shared__ float sd[256];
    sd[t] = mx; __syncthreads();
    for (int off = 128; off > 0; off >>= 1) { if (t < off) sd[t] = fmaxf(sd[t], sd[t + off]); __syncthreads(); }
    mx = sd[0]; __syncthreads();
    float sum = 0.f;
#pragma unroll
    for (int j = 0; j < 4; j++) { v[j] = expf(v[j] - mx); sum += v[j]; }
    sd[t] = sum; __syncthreads();
    for (int off = 128; off > 0; off >>= 1) { if (t < off) sd[t] += sd[t + off]; __syncthreads(); }
    float inv = 1.f / sd[0];
#pragma unroll
    for (int j = 0; j < 4; j++) Or[t + j * 256] = v[j] * inv;
}

// 512 threads: (32, 16)
__global__ void softmax_col_kernel(const float* __restrict__ L, float* __restrict__ O) {
    int b = blockIdx.y;
    int s = blockIdx.x * 32 + threadIdx.x;
    int ty = threadIdx.y;   // 0..15
    const float* Lb = L + (size_t)b * DM * DS;
    float* Ob = O + (size_t)b * DM * DS;
    __shared__ float red[16][32];
    float mx = -1e30f;
    for (int m = ty; m < DM; m += 16) mx = fmaxf(mx, Lb[(size_t)m * DS + s]);
    red[ty][threadIdx.x] = mx; __syncthreads();
    if (ty == 0) {
        float v = red[0][threadIdx.x];
#pragma unroll
        for (int i = 1; i < 16; i++) v = fmaxf(v, red[i][threadIdx.x]);
        red[0][threadIdx.x] = v;
    }
    __syncthreads();
    mx = red[0][threadIdx.x]; __syncthreads();
    float sum = 0.f;
    for (int m = ty; m < DM; m += 16) sum += expf(Lb[(size_t)m * DS + s] - mx);
    red[ty][threadIdx.x] = sum; __syncthreads();
    if (ty == 0) {
        float v = 0.f;
#pragma unroll
        for (int i = 0; i < 16; i++) v += red[i][threadIdx.x];
        red[0][threadIdx.x] = v;
    }
    __syncthreads();
    float inv = 1.f / red[0][threadIdx.x];
    for (int m = ty; m < DM; m += 16)
        Ob[(size_t)m * DS + s] = expf(Lb[(size_t)m * DS + s] - mx) * inv;
}

// LayerNorm: read Xs [b][n*16+p][d], write LN [n][b*16+p][d]
__global__ void layernorm_kernel(const float* __restrict__ X, float* __restrict__ Yo,
                                 const float* __restrict__ g, const float* __restrict__ bb) {
    int row = blockIdx.x;
    int b = row >> 10;
    int slot = row & 1023;
    int n = slot >> 4;
    int p = slot & 15;
    const float* Xr = X + (size_t)row * DD;
    float* Yr = Yo + ((size_t)n * 128 + b * 16 + p) * DD;
    __shared__ float sh[DD];
    __shared__ float red[256];
    int t = threadIdx.x;
    float ls = 0.f;
    for (int j = t; j < DD; j += 256) { float v = Xr[j]; sh[j] = v; ls += v; }
    red[t] = ls; __syncthreads();
    for (int off = 128; off > 0; off >>= 1) { if (t < off) red[t] += red[t + off]; __syncthreads(); }
    float mu = red[0] * (1.0f / DD); __syncthreads();
    float lv = 0.f;
    for (int j = t; j < DD; j += 256) { float dv = sh[j] - mu; lv += dv * dv; }
    red[t] = lv; __syncthreads();
    for (int off = 128; off > 0; off >>= 1) { if (t < off) red[t] += red[t + off]; __syncthreads(); }
    float is = rsqrtf(red[0] * (1.0f / DD) + 1e-5f); __syncthreads();
    for (int j = t; j < DD; j += 256)
        Yr[j] = (sh[j] - mu) * is * g[n * DD + j] + bb[n * DD + j];
}

// ================= mma.sync GEMM =================
// 512 threads, 16 warps 4x4; warp tile 32x32; CTA tile 128x128, kc=32.
// fp16 2-term split (A = hi+lo exact; B = rn(fp16)); double-buffered, ONE sync/iter.
// TA/TB: 0 = row-major [row][K], 1 = K-major [K][row]
// EPI: 0 none, 1 +bias, 2 +bias+gelu ; CSC: 1 = scattered output rows
template <int TA, int TB, int EPI, int CSC>
__global__ void __launch_bounds__(512)
gemm_mma(const float* __restrict__ A, const float* __restrict__ B,
         float* __restrict__ C, const float* __restrict__ bias,
         int K, int lda, int ldb, int ldc,
         long long aBS, long long bBS, long long cBS, int biasBS, long long c_sb) {
    constexpr int ASZ1 = TA ? 32 * 272 : 128 * 80;
    constexpr int BSZ1 = TB ? 32 * 272 : 128 * 80;
    constexpr int STAGE = 2 * ASZ1 + BSZ1;       // A hi + A lo + B hi
    extern __shared__ char smem[];
    const uint32_t sm0 = smem_to_u32(smem);

    const int tid = threadIdx.x;
    const int l = tid & 31;
    const int wid = tid >> 5;       // 0..15
    const int wm = wid & 3;         // 4 M groups of 32 rows
    const int wn = wid >> 2;        // 4 N groups of 32 cols
    const int z = blockIdx.z;
    const int bm = blockIdx.y * 128;
    const int bn = blockIdx.x * 128;
    const int NC = K >> 5;

    const float* Ab = A + (size_t)z * aBS + (TA ? (size_t)bm : (size_t)bm * lda);
    const float* Bb = B + (size_t)z * bBS + (TB ? (size_t)bn : (size_t)bn * ldb);

    float4 ra[2], rb[2];

    auto LDG = [&](int c) {
        int k0 = c * 32;
#pragma unroll
        for (int i = 0; i < 2; i++) {
            int p = tid + i * 512;
            if (TA) ra[i] = *(const float4*)(Ab + (size_t)(k0 + (p >> 5)) * lda + (p & 31) * 4);
            else    ra[i] = *(const float4*)(Ab + (size_t)(p >> 3) * lda + k0 + (p & 7) * 4);
            if (TB) rb[i] = *(const float4*)(Bb + (size_t)(k0 + (p >> 5)) * ldb + (p & 31) * 4);
            else    rb[i] = *(const float4*)(Bb + (size_t)(p >> 3) * ldb + k0 + (p & 7) * 4);
        }
    };

    auto STS = [&](int s) {
        char* st = smem + s * STAGE;
        char* ahis = st;
        char* alos = st + ASZ1;
        char* bhis = st + 2 * ASZ1;
#pragma unroll
        for (int i = 0; i < 2; i++) {
            int p = tid + i * 512;
            int aoff = TA ? ((p >> 5) * 272 + (p & 31) * 8) : ((p >> 3) * 80 + (p & 7) * 8);
            int boff = TB ? ((p >> 5) * 272 + (p & 31) * 8) : ((p >> 3) * 80 + (p & 7) * 8);
            uint32_t h01, h23, l01, l23;
            split4h(ra[i], h01, h23, l01, l23);
            *(uint2*)(ahis + aoff) = make_uint2(h01, h23);
            *(uint2*)(alos + aoff) = make_uint2(l01, l23);
            hi4h(rb[i], h01, h23);
            *(uint2*)(bhis + boff) = make_uint2(h01, h23);
        }
    };

    float acc[2][4][4];
#pragma unroll
    for (int mt = 0; mt < 2; mt++)
#pragma unroll
        for (int nt = 0; nt < 4; nt++)
#pragma unroll
            for (int q = 0; q < 4; q++) acc[mt][nt][q] = 0.f;

    auto COMPUTE = [&](int s) {
        uint32_t sbA = sm0 + s * STAGE;
        uint32_t sbB = sbA + 2 * ASZ1;
#pragma unroll
        for (int ks = 0; ks < 2; ks++) {
            uint32_t ahi[2][4], alo[2][4];
#pragma unroll
            for (int mt = 0; mt < 2; mt++) {
                int mr = wm * 32 + mt * 16;
                if (TA) {
                    int krow = ks * 16 + (l & 7) + ((l >> 4) << 3);
                    int col = mr + (((l >> 3) & 1) << 3);
                    uint32_t addr = sbA + krow * 272 + col * 2;
                    ldsm_x4_t(ahi[mt], addr);
                    ldsm_x4_t(alo[mt], addr + ASZ1);
                } else {
                    int row = mr + (l & 15);
                    uint32_t addr = sbA + row * 80 + ks * 32 + ((l >> 4) & 1) * 16;
                    ldsm_x4(ahi[mt], addr);
                    ldsm_x4(alo[mt], addr + ASZ1);
                }
            }
#pragma unroll
            for (int np = 0; np < 2; np++) {
                int nr = wn * 32 + np * 16;
                uint32_t bhi[4];
                if (TB) {
                    int krow = ks * 16 + (l & 7) + (((l >> 3) & 1) << 3);
                    int col = nr + ((l >> 4) << 3);
                    uint32_t addr = sbB + krow * 272 + col * 2;
                    ldsm_x4_t(bhi, addr);
                } else {
                    int row = nr + (l & 7) + ((l >> 4) << 3);
                    uint32_t addr = sbB + row * 80 + ks * 32 + (((l >> 3) & 1) << 4);
                    ldsm_x4(bhi, addr);
                }
#pragma unroll
                for (int half = 0; half < 2; half++) {
                    int nt = np * 2 + half;
#pragma unroll
                    for (int mt = 0; mt < 2; mt++) {
                        mma_f16(acc[mt][nt], ahi[mt], bhi + 2 * half);
                        mma_f16(acc[mt][nt], alo[mt], bhi + 2 * half);
                    }
                }
            }
        }
    };

    LDG(0);
    STS(0);
    if (NC > 1) LDG(1);
    __syncthreads();
    for (int c = 0; c < NC; c++) {
        if (c + 1 < NC) STS((c + 1) & 1);
        if (c + 2 < NC) LDG(c + 2);
        COMPUTE(c & 1);
        __syncthreads();
    }

    // ---------------- epilogue via smem staging ----------------
    float* Cs = (float*)smem;   // [128][132]
#pragma unroll
    for (int mt = 0; mt < 2; mt++) {
#pragma unroll
        for (int nt = 0; nt < 4; nt++) {
            int r0 = wm * 32 + mt * 16 + (l >> 2);
            int c0 = wn * 32 + nt * 8 + (l & 3) * 2;
            Cs[r0 * 132 + c0] = acc[mt][nt][0];
            Cs[r0 * 132 + c0 + 1] = acc[mt][nt][1];
            Cs[(r0 + 8) * 132 + c0] = acc[mt][nt][2];
            Cs[(r0 + 8) * 132 + c0 + 1] = acc[mt][nt][3];
        }
    }
    __syncthreads();
    const float* bp = (EPI >= 1) ? (bias + (size_t)z * biasBS + bn) : nullptr;
#pragma unroll 4
    for (int i = 0; i < 32; i++) {
        int idx = i * 512 + tid;
        int r = idx >> 7, cc = idx & 127;
        float v = Cs[r * 132 + cc];
        if (EPI >= 1) v += __ldg(bp + cc);
        if (EPI == 2) v = 0.5f * v * (1.0f + erff(v * 0.70710678118654752440f));
        size_t off;
        if (CSC)
            off = (size_t)z * cBS + (size_t)(r >> 4) * c_sb + (size_t)(r & 15) * ldc + bn + cc;
        else
            off = (size_t)z * cBS + (size_t)(bm + r) * ldc + bn + cc;
        C[off] = v;
    }
}

// ================= host launcher =================
extern "C" void kernel_launch(void* const* d_in, const int* in_sizes, int n_in,
                              void* d_out, int out_size) {
    const float* x    = (const float*)d_in[0];
    const float* phi  = (const float*)d_in[1];
    const float* ln_g = (const float*)d_in[2];
    const float* ln_b = (const float*)d_in[3];
    const float* w1   = (const float*)d_in[4];
    const float* b1   = (const float*)d_in[5];
    const float* w2   = (const float*)d_in[6];
    const float* b2   = (const float*)d_in[7];
    float* out = (float*)d_out;

    float *phin, *logits, *Dbuf, *Cbuf, *Xs, *LN, *hdn, *Ys;
    cudaGetSymbolAddress((void**)&phin, g_phin);
    cudaGetSymbolAddress((void**)&logits, g_logits);
    cudaGetSymbolAddress((void**)&Dbuf, g_D);
    cudaGetSymbolAddress((void**)&Cbuf, g_C);
    cudaGetSymbolAddress((void**)&Xs, g_Xs);
    cudaGetSymbolAddress((void**)&LN, g_LN);
    cudaGetSymbolAddress((void**)&hdn, g_hdn);
    cudaGetSymbolAddress((void**)&Ys, g_Ys);

    // smem: max(2 pipeline stages, epilogue staging 128*132*4 = 67584)
    const int EPI_BYTES = 128 * 132 * 4;
    auto mx = [](int a, int b) { return a > b ? a : b; };
    const int SM00 = mx(2 * (2 * 128 * 80 + 128 * 80), EPI_BYTES);   // 61440 -> 67584
    const int SM11 = mx(2 * (2 * 32 * 272 + 32 * 272), EPI_BYTES);   // 52224 -> 67584
    const int SM01 = mx(2 * (2 * 128 * 80 + 32 * 272), EPI_BYTES);   // 58368 -> 67584
    cudaFuncSetAttribute(gemm_mma<0,0,0,0>, cudaFuncAttributeMaxDynamicSharedMemorySize, SM00);
    cudaFuncSetAttribute(gemm_mma<1,1,0,0>, cudaFuncAttributeMaxDynamicSharedMemorySize, SM11);
    cudaFuncSetAttribute(gemm_mma<0,1,2,0>, cudaFuncAttributeMaxDynamicSharedMemorySize, SM01);
    cudaFuncSetAttribute(gemm_mma<0,1,1,1>, cudaFuncAttributeMaxDynamicSharedMemorySize, SM01);
    cudaFuncSetAttribute(gemm_mma<0,1,0,0>, cudaFuncAttributeMaxDynamicSharedMemorySize, SM01);

    // 1. normalize phi
    phi_norm_kernel<<<(DP * DD + 255) / 256, 256>>>(phi, phin);

    // 2. logits[8192,1024] = x @ phin^T
    gemm_mma<0,0,0,0><<<dim3(DS / 128, (DB * DM) / 128, 1), 512, SM00>>>(
        x, phin, logits, nullptr, DD, DD, DD, DS, 0, 0, 0, 0, 0);

    // 3. softmaxes
    softmax_row_kernel<<<DB * DM, 256>>>(logits, Cbuf);
    softmax_col_kernel<<<dim3(DS / 32, DB), dim3(32, 16)>>>(logits, Dbuf);

    // 4. Xs[b][s][d] = D_b^T @ x_b
    gemm_mma<1,1,0,0><<<dim3(DD / 128, DS / 128, DB), 512, SM11>>>(
        Dbuf, x, Xs, nullptr, DM, DS, DD, DD,
        (long long)DM * DS, (long long)DM * DD, (long long)DS * DD, 0, 0);

    // 5. LayerNorm + gather into expert layout
    layernorm_kernel<<<DB * DS, 256>>>(Xs, LN, ln_g, ln_b);

    // 6. hdn[n][128][h] = LN[n] @ w1[n] + b1, GELU
    gemm_mma<0,1,2,0><<<dim3(DH / 128, 1, DN), 512, SM01>>>(
        LN, w1, hdn, b1, DD, DD, DH, DH,
        (long long)128 * DD, (long long)DD * DH, (long long)128 * DH, DH, 0);

    // 7. Ys[b][n*16+p][d] = hdn[n] @ w2[n] + b2  (scattered C)
    gemm_mma<0,1,1,1><<<dim3(DD / 128, 1, DN), 512, SM01>>>(
        hdn, w2, Ys, b2, DH, DH, DD, DD,
        (long long)128 * DH, (long long)DH * DD, (long long)DP * DD, DD,
        (long long)DS * DD);

    // 8. Y[b][m][d] = C_b @ Ys_b
    gemm_mma<0,1,0,0><<<dim3(DD / 128, DM / 128, DB), 512, SM01>>>(
        Cbuf, Ys, out, nullptr, DS, DS, DD, DD,
        (long long)DM * DS, (long long)DS * DD, (long long)DM * DD, 0, 0);
}

// round 9
// speedup vs baseline: 1.5298x; 1.0534x over previous
#include <cuda_runtime.h>
#include <cuda_bf16.h>
#include <math.h>
#include <cstdint>

// ---------------- dimensions ----------------
#define DB 8
#define DM 1024
#define DD 768
#define DN 64
#define DP 16
#define DH 1536
#define DS 1024   // n*p

// ---------------- scratch ----------------
__device__ float g_phin[DN * DP * DD];
__device__ float g_logits[DB * DM * DS];
__device__ float g_D[DB * DM * DS];
__device__ float g_C[DB * DM * DS];
__device__ float g_Xs[DB * DS * DD];
__device__ float g_LN[DN * DB * DP * DD];       // [n][b*16+p][d]
__device__ float g_hdn[DN * (DB * DP) * DH];    // [n][128][h]
__device__ float g_Ys[DB * DS * DD];            // [b][s][d]

// ================= helpers =================
__device__ __forceinline__ uint32_t smem_to_u32(const void* p) {
    uint32_t a;
    asm("{ .reg .u64 t; cvta.to.shared.u64 t, %1; cvt.u32.u64 %0, t; }" : "=r"(a) : "l"(p));
    return a;
}

// fast split: hi = truncate-to-bf16 (bit mask), lo = rn(x - hi)
__device__ __forceinline__ void split4(float4 v, uint32_t& h01, uint32_t& h23,
                                       uint32_t& l01, uint32_t& l23) {
    uint32_t ux = __float_as_uint(v.x), uy = __float_as_uint(v.y);
    uint32_t uz = __float_as_uint(v.z), uw = __float_as_uint(v.w);
    h01 = __byte_perm(ux, uy, 0x7632);
    h23 = __byte_perm(uz, uw, 0x7632);
    float hx = __uint_as_float(ux & 0xFFFF0000u);
    float hy = __uint_as_float(uy & 0xFFFF0000u);
    float hz = __uint_as_float(uz & 0xFFFF0000u);
    float hw = __uint_as_float(uw & 0xFFFF0000u);
    asm("cvt.rn.bf16x2.f32 %0, %1, %2;" : "=r"(l01) : "f"(v.y - hy), "f"(v.x - hx));
    asm("cvt.rn.bf16x2.f32 %0, %1, %2;" : "=r"(l23) : "f"(v.w - hw), "f"(v.z - hz));
}

__device__ __forceinline__ void ldsm_x4(uint32_t* r, uint32_t addr) {
    asm volatile("ldmatrix.sync.aligned.m8n8.x4.shared.b16 {%0,%1,%2,%3}, [%4];"
                 : "=r"(r[0]), "=r"(r[1]), "=r"(r[2]), "=r"(r[3]) : "r"(addr));
}
__device__ __forceinline__ void ldsm_x4_t(uint32_t* r, uint32_t addr) {
    asm volatile("ldmatrix.sync.aligned.m8n8.x4.trans.shared.b16 {%0,%1,%2,%3}, [%4];"
                 : "=r"(r[0]), "=r"(r[1]), "=r"(r[2]), "=r"(r[3]) : "r"(addr));
}
__device__ __forceinline__ void mma_bf16(float* d, const uint32_t* a, const uint32_t* b) {
    asm volatile(
        "mma.sync.aligned.m16n8k16.row.col.f32.bf16.bf16.f32 "
        "{%0,%1,%2,%3}, {%4,%5,%6,%7}, {%8,%9}, {%0,%1,%2,%3};"
        : "+f"(d[0]), "+f"(d[1]), "+f"(d[2]), "+f"(d[3])
        : "r"(a[0]), "r"(a[1]), "r"(a[2]), "r"(a[3]), "r"(b[0]), "r"(b[1]));
}

// ================= elementwise kernels =================
__global__ void phi_norm_kernel(const float* __restrict__ phi, float* __restrict__ phin) {
    int i = blockIdx.x * blockDim.x + threadIdx.x;
    if (i >= DP * DD) return;
    float s = 0.f;
#pragma unroll 4
    for (int n = 0; n < DN; n++) { float v = phi[n * (DP * DD) + i]; s += v * v; }
    float r = rsqrtf(s + 1e-6f);
#pragma unroll 4
    for (int n = 0; n < DN; n++) phin[n * (DP * DD) + i] = phi[n * (DP * DD) + i] * r;
}

__global__ void softmax_row_kernel(const float* __restrict__ L, float* __restrict__ O) {
    const float* Lr = L + (size_t)blockIdx.x * DS;
    float* Or = O + (size_t)blockIdx.x * DS;
    int t = threadIdx.x;
    float v[4]; float mx = -1e30f;
#pragma unroll
    for (int j = 0; j < 4; j++) { v[j] = Lr[t + j * 256]; mx = fmaxf(mx, v[j]); }
    __shared__ float sd[256];
    sd[t] = mx; __syncthreads();
    for (int off = 128; off > 0; off >>= 1) { if (t < off) sd[t] = fmaxf(sd[t], sd[t + off]); __syncthreads(); }
    mx = sd[0]; __syncthreads();
    float sum = 0.f;
#pragma unroll
    for (int j = 0; j < 4; j++) { v[j] = expf(v[j] - mx); sum += v[j]; }
    sd[t] = sum; __syncthreads();
    for (int off = 128; off > 0; off >>= 1) { if (t < off) sd[t] += sd[t + off]; __syncthreads(); }
    float inv = 1.f / sd[0];
#pragma unroll
    for (int j = 0; j < 4; j++) Or[t + j * 256] = v[j] * inv;
}

// 512 threads: (32, 16)
__global__ void softmax_col_kernel(const float* __restrict__ L, float* __restrict__ O) {
    int b = blockIdx.y;
    int s = blockIdx.x * 32 + threadIdx.x;
    int ty = threadIdx.y;   // 0..15
    const float* Lb = L + (size_t)b * DM * DS;
    float* Ob = O + (size_t)b * DM * DS;
    __shared__ float red[16][32];
    float mx = -1e30f;
    for (int m = ty; m < DM; m += 16) mx = fmaxf(mx, Lb[(size_t)m * DS + s]);
    red[ty][threadIdx.x] = mx; __syncthreads();
    if (ty == 0) {
        float v = red[0][threadIdx.x];
#pragma unroll
        for (int i = 1; i < 16; i++) v = fmaxf(v, red[i][threadIdx.x]);
        red[0][threadIdx.x] = v;
    }
    __syncthreads();
    mx = red[0][threadIdx.x]; __syncthreads();
    float sum = 0.f;
    for (int m = ty; m < DM; m += 16) sum += expf(Lb[(size_t)m * DS + s] - mx);
    red[ty][threadIdx.x] = sum; __syncthreads();
    if (ty == 0) {
        float v = 0.f;
#pragma unroll
        for (int i = 0; i < 16; i++) v += red[i][threadIdx.x];
        red[0][threadIdx.x] = v;
    }
    __syncthreads();
    float inv = 1.f / red[0][threadIdx.x];
    for (int m = ty; m < DM; m += 16)
        Ob[(size_t)m * DS + s] = expf(Lb[(size_t)m * DS + s] - mx) * inv;
}

// LayerNorm: read Xs [b][n*16+p][d], write LN [n][b*16+p][d]
__global__ void layernorm_kernel(const float* __restrict__ X, float* __restrict__ Yo,
                                 const float* __restrict__ g, const float* __restrict__ bb) {
    int row = blockIdx.x;
    int b = row >> 10;
    int slot = row & 1023;
    int n = slot >> 4;
    int p = slot & 15;
    const float* Xr = X + (size_t)row * DD;
    float* Yr = Yo + ((size_t)n * 128 + b * 16 + p) * DD;
    __shared__ float sh[DD];
    __shared__ float red[256];
    int t = threadIdx.x;
    float ls = 0.f;
    for (int j = t; j < DD; j += 256) { float v = Xr[j]; sh[j] = v; ls += v; }
    red[t] = ls; __syncthreads();
    for (int off = 128; off > 0; off >>= 1) { if (t < off) red[t] += red[t + off]; __syncthreads(); }
    float mu = red[0] * (1.0f / DD); __syncthreads();
    float lv = 0.f;
    for (int j = t; j < DD; j += 256) { float dv = sh[j] - mu; lv += dv * dv; }
    red[t] = lv; __syncthreads();
    for (int off = 128; off > 0; off >>= 1) { if (t < off) red[t] += red[t + off]; __syncthreads(); }
    float is = rsqrtf(red[0] * (1.0f / DD) + 1e-5f); __syncthreads();
    for (int j = t; j < DD; j += 256)
        Yr[j] = (sh[j] - mu) * is * g[n * DD + j] + bb[n * DD + j];
}

// ================= mma.sync GEMM =================
// 256 threads, 8 warps in 4(M)x2(N); warp tile 32x32; CTA tile 128x64, kc=32.
// bf16 3-term split, double-buffered, ONE sync/iter, 2 CTAs/SM.
// TA/TB: 0 = row-major [row][K], 1 = K-major [K][row]
// EPI: 0 none, 1 +bias, 2 +bias+gelu ; CSC: 1 = scattered output rows
template <int TA, int TB, int EPI, int CSC>
__global__ void __launch_bounds__(256, 2)
gemm_mma(const float* __restrict__ A, const float* __restrict__ B,
         float* __restrict__ C, const float* __restrict__ bias,
         int K, int lda, int ldb, int ldc,
         long long aBS, long long bBS, long long cBS, int biasBS, long long c_sb) {
    constexpr int ASZ1 = TA ? 32 * 272 : 128 * 80;   // one plane of A tile (128 x kc)
    constexpr int BSZ1 = TB ? 32 * 144 : 64 * 80;    // one plane of B tile (64 x kc)
    constexpr int STAGE = 2 * ASZ1 + 2 * BSZ1;
    extern __shared__ char smem[];
    const uint32_t sm0 = smem_to_u32(smem);

    const int tid = threadIdx.x;
    const int l = tid & 31;
    const int wid = tid >> 5;       // 0..7
    const int wm = wid & 3;         // 4 M groups of 32 rows
    const int wn = wid >> 2;        // 2 N groups of 32 cols
    const int z = blockIdx.z;
    const int bm = blockIdx.y * 128;
    const int bn = blockIdx.x * 64;
    const int NC = K >> 5;

    const float* Ab = A + (size_t)z * aBS + (TA ? (size_t)bm : (size_t)bm * lda);
    const float* Bb = B + (size_t)z * bBS + (TB ? (size_t)bn : (size_t)bn * ldb);

    float4 ra[4], rb[2];

    auto LDG = [&](int c) {
        int k0 = c * 32;
#pragma unroll
        for (int i = 0; i < 4; i++) {
            int p = tid + i * 256;   // 1024 float4 of A
            if (TA) ra[i] = *(const float4*)(Ab + (size_t)(k0 + (p >> 5)) * lda + (p & 31) * 4);
            else    ra[i] = *(const float4*)(Ab + (size_t)(p >> 3) * lda + k0 + (p & 7) * 4);
        }
#pragma unroll
        for (int i = 0; i < 2; i++) {
            int p = tid + i * 256;   // 512 float4 of B
            if (TB) rb[i] = *(const float4*)(Bb + (size_t)(k0 + (p >> 4)) * ldb + (p & 15) * 4);
            else    rb[i] = *(const float4*)(Bb + (size_t)(p >> 3) * ldb + k0 + (p & 7) * 4);
        }
    };

    auto STS = [&](int s) {
        char* st = smem + s * STAGE;
        char* ahis = st;
        char* alos = st + ASZ1;
        char* bhis = st + 2 * ASZ1;
        char* blos = st + 2 * ASZ1 + BSZ1;
#pragma unroll
        for (int i = 0; i < 4; i++) {
            int p = tid + i * 256;
            int aoff = TA ? ((p >> 5) * 272 + (p & 31) * 8) : ((p >> 3) * 80 + (p & 7) * 8);
            uint32_t h01, h23, l01, l23;
            split4(ra[i], h01, h23, l01, l23);
            *(uint2*)(ahis + aoff) = make_uint2(h01, h23);
            *(uint2*)(alos + aoff) = make_uint2(l01, l23);
        }
#pragma unroll
        for (int i = 0; i < 2; i++) {
            int p = tid + i * 256;
            int boff = TB ? ((p >> 4) * 144 + (p & 15) * 8) : ((p >> 3) * 80 + (p & 7) * 8);
            uint32_t h01, h23, l01, l23;
            split4(rb[i], h01, h23, l01, l23);
            *(uint2*)(bhis + boff) = make_uint2(h01, h23);
            *(uint2*)(blos + boff) = make_uint2(l01, l23);
        }
    };

    float acc[2][4][4];
#pragma unroll
    for (int mt = 0; mt < 2; mt++)
#pragma unroll
        for (int nt = 0; nt < 4; nt++)
#pragma unroll
            for (int q = 0; q < 4; q++) acc[mt][nt][q] = 0.f;

    auto COMPUTE = [&](int s) {
        uint32_t sbA = sm0 + s * STAGE;
        uint32_t sbB = sbA + 2 * ASZ1;
#pragma unroll
        for (int ks = 0; ks < 2; ks++) {
            uint32_t ahi[2][4], alo[2][4];
#pragma unroll
            for (int mt = 0; mt < 2; mt++) {
                int mr = wm * 32 + mt * 16;
                if (TA) {
                    int krow = ks * 16 + (l & 7) + ((l >> 4) << 3);
                    int col = mr + (((l >> 3) & 1) << 3);
                    uint32_t addr = sbA + krow * 272 + col * 2;
                    ldsm_x4_t(ahi[mt], addr);
                    ldsm_x4_t(alo[mt], addr + ASZ1);
                } else {
                    int row = mr + (l & 15);
                    uint32_t addr = sbA + row * 80 + ks * 32 + ((l >> 4) & 1) * 16;
                    ldsm_x4(ahi[mt], addr);
                    ldsm_x4(alo[mt], addr + ASZ1);
                }
            }
#pragma unroll
            for (int np = 0; np < 2; np++) {
                int nr = wn * 32 + np * 16;
                uint32_t bhi[4], blo[4];
                if (TB) {
                    int krow = ks * 16 + (l & 7) + (((l >> 3) & 1) << 3);
                    int col = nr + ((l >> 4) << 3);
                    uint32_t addr = sbB + krow * 144 + col * 2;
                    ldsm_x4_t(bhi, addr);
                    ldsm_x4_t(blo, addr + BSZ1);
                } else {
                    int row = nr + (l & 7) + ((l >> 4) << 3);
                    uint32_t addr = sbB + row * 80 + ks * 32 + (((l >> 3) & 1) << 4);
                    ldsm_x4(bhi, addr);
                    ldsm_x4(blo, addr + BSZ1);
                }
#pragma unroll
                for (int half = 0; half < 2; half++) {
                    int nt = np * 2 + half;
#pragma unroll
                    for (int mt = 0; mt < 2; mt++) {
                        mma_bf16(acc[mt][nt], ahi[mt], bhi + 2 * half);
                        mma_bf16(acc[mt][nt], alo[mt], bhi + 2 * half);
                        mma_bf16(acc[mt][nt], ahi[mt], blo + 2 * half);
                    }
                }
            }
        }
    };

    LDG(0);
    STS(0);
    if (NC > 1) LDG(1);
    __syncthreads();
    for (int c = 0; c < NC; c++) {
        if (c + 1 < NC) STS((c + 1) & 1);
        if (c + 2 < NC) LDG(c + 2);
        COMPUTE(c & 1);
        __syncthreads();
    }

    // ---------------- epilogue via smem staging ----------------
    float* Cs = (float*)smem;   // [128][68]
#pragma unroll
    for (int mt = 0; mt < 2; mt++) {
#pragma unroll
        for (int nt = 0; nt < 4; nt++) {
            int r0 = wm * 32 + mt * 16 + (l >> 2);
            int c0 = wn * 32 + nt * 8 + (l & 3) * 2;
            Cs[r0 * 68 + c0] = acc[mt][nt][0];
            Cs[r0 * 68 + c0 + 1] = acc[mt][nt][1];
            Cs[(r0 + 8) * 68 + c0] = acc[mt][nt][2];
            Cs[(r0 + 8) * 68 + c0 + 1] = acc[mt][nt][3];
        }
    }
    __syncthreads();
    const float* bp = (EPI >= 1) ? (bias + (size_t)z * biasBS + bn) : nullptr;
#pragma unroll 4
    for (int i = 0; i < 32; i++) {
        int idx = i * 256 + tid;       // 8192 elements
        int r = idx >> 6, cc = idx & 63;
        float v = Cs[r * 68 + cc];
        if (EPI >= 1) v += __ldg(bp + cc);
        if (EPI == 2) v = 0.5f * v * (1.0f + erff(v * 0.70710678118654752440f));
        size_t off;
        if (CSC)
            off = (size_t)z * cBS + (size_t)(r >> 4) * c_sb + (size_t)(r & 15) * ldc + bn + cc;
        else
            off = (size_t)z * cBS + (size_t)(bm + r) * ldc + bn + cc;
        C[off] = v;
    }
}

// ================= host launcher =================
extern "C" void kernel_launch(void* const* d_in, const int* in_sizes, int n_in,
                              void* d_out, int out_size) {
    const float* x    = (const float*)d_in[0];
    const float* phi  = (const float*)d_in[1];
    const float* ln_g = (const float*)d_in[2];
    const float* ln_b = (const float*)d_in[3];
    const float* w1   = (const float*)d_in[4];
    const float* b1   = (const float*)d_in[5];
    const float* w2   = (const float*)d_in[6];
    const float* b2   = (const float*)d_in[7];
    float* out = (float*)d_out;

    float *phin, *logits, *Dbuf, *Cbuf, *Xs, *LN, *hdn, *Ys;
    cudaGetSymbolAddress((void**)&phin, g_phin);
    cudaGetSymbolAddress((void**)&logits, g_logits);
    cudaGetSymbolAddress((void**)&Dbuf, g_D);
    cudaGetSymbolAddress((void**)&Cbuf, g_C);
    cudaGetSymbolAddress((void**)&Xs, g_Xs);
    cudaGetSymbolAddress((void**)&LN, g_LN);
    cudaGetSymbolAddress((void**)&hdn, g_hdn);
    cudaGetSymbolAddress((void**)&Ys, g_Ys);

    // smem: max(2 pipeline stages, epilogue staging 128*68*4 = 34816)
    const int EPI_BYTES = 128 * 68 * 4;
    auto mx = [](int a, int b) { return a > b ? a : b; };
    const int SM00 = mx(2 * (2 * 128 * 80 + 2 * 64 * 80), EPI_BYTES);    // 61440
    const int SM11 = mx(2 * (2 * 32 * 272 + 2 * 32 * 144), EPI_BYTES);   // 53248
    const int SM01 = mx(2 * (2 * 128 * 80 + 2 * 32 * 144), EPI_BYTES);   // 59392
    cudaFuncSetAttribute(gemm_mma<0,0,0,0>, cudaFuncAttributeMaxDynamicSharedMemorySize, SM00);
    cudaFuncSetAttribute(gemm_mma<1,1,0,0>, cudaFuncAttributeMaxDynamicSharedMemorySize, SM11);
    cudaFuncSetAttribute(gemm_mma<0,1,2,0>, cudaFuncAttributeMaxDynamicSharedMemorySize, SM01);
    cudaFuncSetAttribute(gemm_mma<0,1,1,1>, cudaFuncAttributeMaxDynamicSharedMemorySize, SM01);
    cudaFuncSetAttribute(gemm_mma<0,1,0,0>, cudaFuncAttributeMaxDynamicSharedMemorySize, SM01);

    // 1. normalize phi
    phi_norm_kernel<<<(DP * DD + 255) / 256, 256>>>(phi, phin);

    // 2. logits[8192,1024] = x @ phin^T    (grid 16x64 = 1024 CTAs)
    gemm_mma<0,0,0,0><<<dim3(DS / 64, (DB * DM) / 128, 1), 256, SM00>>>(
        x, phin, logits, nullptr, DD, DD, DD, DS, 0, 0, 0, 0, 0);

    // 3. softmaxes
    softmax_row_kernel<<<DB * DM, 256>>>(logits, Cbuf);
    softmax_col_kernel<<<dim3(DS / 32, DB), dim3(32, 16)>>>(logits, Dbuf);

    // 4. Xs[b][s][d] = D_b^T @ x_b    (grid 12x8x8 = 768 CTAs)
    gemm_mma<1,1,0,0><<<dim3(DD / 64, DS / 128, DB), 256, SM11>>>(
        Dbuf, x, Xs, nullptr, DM, DS, DD, DD,
        (long long)DM * DS, (long long)DM * DD, (long long)DS * DD, 0, 0);

    // 5. LayerNorm + gather into expert layout
    layernorm_kernel<<<DB * DS, 256>>>(Xs, LN, ln_g, ln_b);

    // 6. hdn[n][128][h] = LN[n] @ w1[n] + b1, GELU   (grid 24x1x64 = 1536 CTAs)
    gemm_mma<0,1,2,0><<<dim3(DH / 64, 1, DN), 256, SM01>>>(
        LN, w1, hdn, b1, DD, DD, DH, DH,
        (long long)128 * DD, (long long)DD * DH, (long long)128 * DH, DH, 0);

    // 7. Ys[b][n*16+p][d] = hdn[n] @ w2[n] + b2  (scattered C; 12x1x64 = 768 CTAs)
    gemm_mma<0,1,1,1><<<dim3(DD / 64, 1, DN), 256, SM01>>>(
        hdn, w2, Ys, b2, DH, DH, DD, DD,
        (long long)128 * DH, (long long)DH * DD, (long long)DP * DD, DD,
        (long long)DS * DD);

    // 8. Y[b][m][d] = C_b @ Ys_b   (grid 12x8x8 = 768 CTAs)
    gemm_mma<0,1,0,0><<<dim3(DD / 64, DM / 128, DB), 256, SM01>>>(
        Cbuf, Ys, out, nullptr, DS, DS, DD, DD,
        (long long)DM * DS, (long long)DS * DD, (long long)DM * DD, 0, 0);
}